// round 10
// baseline (speedup 1.0000x reference)
#include <cuda_runtime.h>
#include <math.h>

#define BB 8192
#define TT 8
#define EE 256
#define MM 20
#define NN (BB*MM)          // 163840 rows after mode expansion
#define NPRED (NN*24)       // predictions element count

typedef unsigned long long ull;

// ---------------- scratch (static device memory; no allocs) ----------------
__device__ float g_hA[BB*EE];
__device__ float g_hB[BB*EE];
__device__ float g_c [BB*EE];
__device__ float g_ys0[(size_t)TT*BB*EE];
__device__ float g_Cw[(size_t)MM*EE*EE];
__device__ float g_Cb[MM*EE];
__device__ float g_x1[(size_t)NN*EE];
__device__ float g_mm[(size_t)NN*EE];

__device__ __forceinline__ float sigf(float x){
    return __fdividef(1.f, 1.f + __expf(-x));
}
__device__ __forceinline__ float tanhfast(float x){
    return __fdividef(2.f, 1.f + __expf(-2.f*x)) - 1.f;
}

// ---------------- packed f32x2 helpers (FFMA2 only reachable via PTX) ------
__device__ __forceinline__ ull pack2(float lo, float hi){
    ull r;
    asm("mov.b64 %0, {%1, %2};" : "=l"(r) : "f"(lo), "f"(hi));
    return r;
}
__device__ __forceinline__ void fma2(ull &d, ull a, ull b){
    asm("fma.rn.f32x2 %0, %1, %2, %0;" : "+l"(d) : "l"(a), "l"(b));
}
__device__ __forceinline__ float2 unpack2(ull v){
    float lo, hi;
    asm("mov.b64 {%0, %1}, %2;" : "=f"(lo), "=f"(hi) : "l"(v));
    return make_float2(lo, hi);
}

// ---------------- B-tile prefetch / store, 256-thread depth-32 -------------
// pair p covers source rows (2p, 2p+1); Bp[p*33 + k] = (row2p[k], row2p+1[k])
template<int NP>
__device__ __forceinline__ void prefetch_bpairs(float2* __restrict__ v,
                                                const float* __restrict__ src0,
                                                size_t rowstride, int k0, int tid){
    #pragma unroll
    for (int i = 0; i < NP/8; i++){
        int li = tid + i*256; int p = li >> 5, k = li & 31;
        const float* s = src0 + (size_t)(2*p)*rowstride + k0 + k;
        v[i] = make_float2(s[0], s[rowstride]);
    }
}
template<int NP>
__device__ __forceinline__ void store_bpairs(float2* __restrict__ Bp,
                                             const float2* __restrict__ v, int tid){
    #pragma unroll
    for (int i = 0; i < NP/8; i++){
        int li = tid + i*256; int p = li >> 5, k = li & 31;
        Bp[p*33 + k] = v[i];
    }
}

// Load 64 rows x 256 cols of activations into xs (stride 260), 256 threads.
__device__ __forceinline__ void load_xs64(float* __restrict__ xs,
                                          const float* __restrict__ src,
                                          int tid){
    #pragma unroll
    for (int i = 0; i < 16; i++){
        int li = tid + i*256; int r = li >> 6, c = (li & 63)*4;
        *(float4*)&xs[r*260 + c] = *(const float4*)&src[(size_t)r*EE + c];
    }
}

// 32-deep k-slab of an 8-row x NPAIR-colpair f32x2 GEMM tile (Bp stride 33).
template<int NPAIR>
__device__ __forceinline__ void gemm8_tile32(
    const float* __restrict__ xr, const float2* __restrict__ Bp,
    int l, ull* acc)
{
    #pragma unroll
    for (int k4 = 0; k4 < 32; k4 += 4){
        float Ar[8][4];
        #pragma unroll
        for (int r = 0; r < 8; r++){
            float4 t = *(const float4*)(xr + r*260 + k4);
            Ar[r][0]=t.x; Ar[r][1]=t.y; Ar[r][2]=t.z; Ar[r][3]=t.w;
        }
        #pragma unroll
        for (int kk = 0; kk < 4; kk++){
            ull bb[NPAIR];
            #pragma unroll
            for (int j = 0; j < NPAIR; j++)
                bb[j] = *(const ull*)&Bp[(l + 32*j)*33 + k4 + kk];
            #pragma unroll
            for (int r = 0; r < 8; r++){
                ull pr = pack2(Ar[r][kk], Ar[r][kk]);
                #pragma unroll
                for (int j = 0; j < NPAIR; j++)
                    fma2(acc[r*NPAIR + j], pr, bb[j]);
            }
        }
    }
}

// ---------------- 128-thread depth-16 variants (for 2-CTA ffn) -------------
// Bp stride 17 float2 (odd -> conflict-free).
__device__ __forceinline__ void load_xs32_128(float* __restrict__ xs,
                                              const float* __restrict__ src,
                                              int tid){
    #pragma unroll
    for (int i = 0; i < 16; i++){
        int li = tid + i*128; int r = li >> 6, c = (li & 63)*4;
        *(float4*)&xs[r*260 + c] = *(const float4*)&src[(size_t)r*EE + c];
    }
}
__device__ __forceinline__ void prefetch_bp16_128(float2* __restrict__ v,
                                                  const float* __restrict__ src0,
                                                  size_t rowstride, int k0, int tid){
    #pragma unroll
    for (int i = 0; i < 16; i++){
        int li = tid + i*128; int p = li >> 4, k = li & 15;
        const float* s = src0 + (size_t)(2*p)*rowstride + k0 + k;
        v[i] = make_float2(s[0], s[rowstride]);
    }
}
__device__ __forceinline__ void store_bp16_128(float2* __restrict__ Bp,
                                               const float2* __restrict__ v, int tid){
    #pragma unroll
    for (int i = 0; i < 16; i++){
        int li = tid + i*128; int p = li >> 4, k = li & 15;
        Bp[p*17 + k] = v[i];
    }
}
template<int NPAIR>
__device__ __forceinline__ void gemm8_tile16(
    const float* __restrict__ xr, const float2* __restrict__ Bp,
    int l, ull* acc)
{
    #pragma unroll
    for (int k4 = 0; k4 < 16; k4 += 4){
        float Ar[8][4];
        #pragma unroll
        for (int r = 0; r < 8; r++){
            float4 t = *(const float4*)(xr + r*260 + k4);
            Ar[r][0]=t.x; Ar[r][1]=t.y; Ar[r][2]=t.z; Ar[r][3]=t.w;
        }
        #pragma unroll
        for (int kk = 0; kk < 4; kk++){
            ull bb[NPAIR];
            #pragma unroll
            for (int j = 0; j < NPAIR; j++)
                bb[j] = *(const ull*)&Bp[(l + 32*j)*17 + k4 + kk];
            #pragma unroll
            for (int r = 0; r < 8; r++){
                ull pr = pack2(Ar[r][kk], Ar[r][kk]);
                #pragma unroll
                for (int j = 0; j < NPAIR; j++)
                    fma2(acc[r*NPAIR + j], pr, bb[j]);
            }
        }
    }
}

// ---------------- fold: Cw[m,o,e] = sum_f out_w[m,o,f] * Wv[m,f,e] ----------------
__global__ void fold_cw(const float* __restrict__ inW, const float* __restrict__ outW){
    __shared__ float As[32][33];
    __shared__ float Bs[32][33];
    int m  = blockIdx.z;
    int o0 = blockIdx.y*32;
    int e0 = blockIdx.x*32;
    int tid = threadIdx.x; int tx = tid & 15, ty = tid >> 4;
    float acc00=0.f, acc01=0.f, acc10=0.f, acc11=0.f;
    for (int f0 = 0; f0 < EE; f0 += 32){
        __syncthreads();
        #pragma unroll
        for (int i = 0; i < 4; i++){
            int li = tid + i*256; int r = li >> 5, c = li & 31;
            As[r][c] = outW[((size_t)(m*EE + o0 + r))*EE + f0 + c];
            Bs[r][c] = inW [((size_t)(m*768 + 512 + f0 + r))*EE + e0 + c];
        }
        __syncthreads();
        #pragma unroll
        for (int f = 0; f < 32; f++){
            float a0 = As[ty*2+0][f], a1 = As[ty*2+1][f];
            float b0 = Bs[f][tx*2+0], b1 = Bs[f][tx*2+1];
            acc00 += a0*b0; acc01 += a0*b1; acc10 += a1*b0; acc11 += a1*b1;
        }
    }
    size_t base = ((size_t)(m*EE + o0 + ty*2))*EE + e0 + tx*2;
    g_Cw[base]      = acc00;
    g_Cw[base+1]    = acc01;
    g_Cw[base+EE]   = acc10;
    g_Cw[base+EE+1] = acc11;
}

// Cb[m,o] = sum_f b_v[m,f]*out_w[m,o,f] + out_b[m,o]
__global__ void fold_cb(const float* __restrict__ inB, const float* __restrict__ outW,
                        const float* __restrict__ outB){
    int m = blockIdx.x, o = threadIdx.x;
    const float* wrow = outW + ((size_t)(m*EE + o))*EE;
    const float* bv   = inB + m*768 + 512;
    float acc = 0.f;
    for (int f = 0; f < EE; f++) acc += bv[f]*wrow[f];
    g_Cb[m*EE + o] = acc + outB[m*EE + o];
}

// ---------------- LSTM step, f32x2 8-row tiles (round-6 inline B fill) -----
// 128 regs -> 2 CTAs/SM. dyn smem: xs[64*260] + Bp f2[128*33] = 100352 B
template<int LAYER>
__global__ void __launch_bounds__(256) lstm_step(
    const float* __restrict__ xin,
    const float* __restrict__ wih, const float* __restrict__ whh,
    const float* __restrict__ bih, const float* __restrict__ bhh,
    int t)
{
    extern __shared__ float sm[];
    float*  xs = sm;                       // [64][260]
    float2* Bp = (float2*)(sm + 64*260);   // [128][33]
    const float* hin  = (t & 1) ? g_hB : g_hA;
    float*       hout = (t & 1) ? g_hA : g_hB;
    int tid = threadIdx.x, l = tid & 31, w = tid >> 5;
    int br = blockIdx.x*64, u0 = blockIdx.y*64;

    ull acc[32];
    #pragma unroll
    for (int i = 0; i < 32; i++) acc[i] = 0ull;

    const int npass = (LAYER == 1) ? 2 : 1;
    for (int pass = 0; pass < npass; pass++){
        const float* Am; const float* Bm;
        if (LAYER == 1 && pass == 0){ Am = g_ys0 + (size_t)t*BB*EE; Bm = wih; }
        else {
            if (t == 0) continue;          // h == 0, skip recurrent GEMM
            Am = hin; Bm = whh;
        }
        __syncthreads();                   // protect xs from prior-pass readers
        load_xs64(xs, Am + (size_t)br*EE, tid);
        for (int k0 = 0; k0 < EE; k0 += 32){
            __syncthreads();
            #pragma unroll
            for (int i = 0; i < 16; i++){
                int li = tid + i*256; int p = li >> 5, k = li & 31;
                int gate = p >> 5, up = p & 31;
                size_t j0 = (size_t)(gate*256 + u0 + 2*up);
                Bp[p*33 + k] = make_float2(Bm[j0*EE + k0 + k],
                                           Bm[(j0+1)*EE + k0 + k]);
            }
            __syncthreads();
            gemm8_tile32<4>(&xs[(8*w)*260 + k0], Bp, l, acc);
        }
    }

    // epilogue: thread owns rows br+8w+rr (rr<8), units u0+2l, u0+2l+1.
    int ubase = u0 + 2*l;
    float2 bs[4]; float4 w4[4];
    #pragma unroll
    for (int g = 0; g < 4; g++){
        int j = g*256 + ubase;
        bs[g] = make_float2(bih[j] + bhh[j], bih[j+1] + bhh[j+1]);
        if (LAYER == 0) w4[g] = *(const float4*)&wih[2*j];
    }
    #pragma unroll
    for (int rr = 0; rr < 8; rr++){
        int row = br + 8*w + rr;
        float2 pre[4];
        #pragma unroll
        for (int g = 0; g < 4; g++){
            pre[g] = unpack2(acc[rr*4 + g]);
            pre[g].x += bs[g].x; pre[g].y += bs[g].y;
        }
        if (LAYER == 0){
            float2 xv = *(const float2*)&xin[row*TT*2 + t*2];
            #pragma unroll
            for (int g = 0; g < 4; g++){
                pre[g].x += xv.x*w4[g].x + xv.y*w4[g].y;
                pre[g].y += xv.x*w4[g].z + xv.y*w4[g].w;
            }
        }
        int idx = row*EE + ubase;
        float2 cold = make_float2(0.f, 0.f);
        if (t != 0) cold = *(const float2*)&g_c[idx];
        float igx = sigf(pre[0].x), fgx = sigf(pre[1].x);
        float ggx = tanhfast(pre[2].x), ogx = sigf(pre[3].x);
        float igy = sigf(pre[0].y), fgy = sigf(pre[1].y);
        float ggy = tanhfast(pre[2].y), ogy = sigf(pre[3].y);
        float cnx = fgx*cold.x + igx*ggx;
        float cny = fgy*cold.y + igy*ggy;
        float2 hn = make_float2(ogx*tanhfast(cnx), ogy*tanhfast(cny));
        *(float2*)&g_c[idx] = make_float2(cnx, cny);
        *(float2*)&hout[idx] = hn;
        if (LAYER == 0) *(float2*)&g_ys0[(size_t)t*BB*EE + idx] = hn;
    }
}

// ---------------- attn (folded) + LN1, f32x2 8-row, pipelined --------------
// grid (BB/64, MM), 256 threads. dyn smem: xs[64*260] + Bp f2[128*33] = 100352 B
__global__ void __launch_bounds__(256) attn_ln1(const float* __restrict__ g1,
                                                const float* __restrict__ b1){
    extern __shared__ float sm[];
    float*  xs = sm;                       // [64][260]
    float2* Bp = (float2*)(sm + 64*260);   // [128][33]
    int tid = threadIdx.x, l = tid & 31, w = tid >> 5;
    int b0 = blockIdx.x*64, m = blockIdx.y;

    load_xs64(xs, g_hA + (size_t)b0*EE, tid);

    ull acc[32];
    #pragma unroll
    for (int i = 0; i < 32; i++) acc[i] = 0ull;

    const float* cwm = g_Cw + (size_t)m*EE*EE;
    float2 pf[16];
    prefetch_bpairs<128>(pf, cwm, EE, 0, tid);
    for (int k0 = 0; k0 < EE; k0 += 32){
        __syncthreads();
        store_bpairs<128>(Bp, pf, tid);
        __syncthreads();
        if (k0 + 32 < EE) prefetch_bpairs<128>(pf, cwm, EE, k0 + 32, tid);
        gemm8_tile32<4>(&xs[(8*w)*260 + k0], Bp, l, acc);
    }

    float2 cb[4], g1v[4], b1v[4];
    #pragma unroll
    for (int j = 0; j < 4; j++){
        int c = 2*(l + 32*j);
        cb[j]  = *(const float2*)&g_Cb[m*EE + c];
        g1v[j] = *(const float2*)&g1[c];
        b1v[j] = *(const float2*)&b1[c];
    }
    #pragma unroll
    for (int rr = 0; rr < 8; rr++){
        float vv[8];
        #pragma unroll
        for (int j = 0; j < 4; j++){
            float2 f = unpack2(acc[rr*4 + j]);
            vv[2*j+0] = f.x + cb[j].x;
            vv[2*j+1] = f.y + cb[j].y;
        }
        float s = 0.f;
        #pragma unroll
        for (int q = 0; q < 8; q++) s += vv[q];
        #pragma unroll
        for (int o = 16; o; o >>= 1) s += __shfl_xor_sync(0xffffffffu, s, o);
        float mean = s * (1.f/256.f);
        float vs = 0.f;
        #pragma unroll
        for (int q = 0; q < 8; q++){ float d = vv[q]-mean; vs += d*d; }
        #pragma unroll
        for (int o = 16; o; o >>= 1) vs += __shfl_xor_sync(0xffffffffu, vs, o);
        float inv = rsqrtf(vs*(1.f/256.f) + 1e-5f);
        size_t base = ((size_t)(b0 + 8*w + rr)*MM + m)*EE;
        #pragma unroll
        for (int j = 0; j < 4; j++){
            int c = 2*(l + 32*j);
            float2 o2 = make_float2((vv[2*j+0]-mean)*inv*g1v[j].x + b1v[j].x,
                                    (vv[2*j+1]-mean)*inv*g1v[j].y + b1v[j].y);
            *(float2*)&g_x1[base + c] = o2;
        }
    }
}

// ---------------- fused FFN + LN2, 128-thread 32-row depth-16, 2 CTAs/SM ---
// grid NN/32 = 5120, 128 threads. dyn smem: xs[32*260]+Hs[32*260]+Bp f2[128*17]
// = 33280 + 33280 + 17408 = 83968 B -> 2 CTAs/SM.
__global__ void __launch_bounds__(128) ffn_ln2(
    const float* __restrict__ w1, const float* __restrict__ b1,
    const float* __restrict__ w2, const float* __restrict__ b2,
    const float* __restrict__ g2, const float* __restrict__ bb2)
{
    extern __shared__ float sm[];
    float*  xs = sm;                         // [32][260]
    float*  Hs = sm + 32*260;                // [32][260]
    float2* Bp = (float2*)(sm + 2*32*260);   // [128][17]
    int tid = threadIdx.x, l = tid & 31, w = tid >> 5;   // w in 0..3
    int r0 = blockIdx.x*32;

    load_xs32_128(xs, g_x1 + (size_t)r0*EE, tid);

    ull yacc[32];
    #pragma unroll
    for (int i = 0; i < 32; i++) yacc[i] = 0ull;

    float2 pf[16];
    prefetch_bp16_128(pf, w1, EE, 0, tid);
    for (int jc = 0; jc < 4; jc++){
        ull hacc[32];
        #pragma unroll
        for (int i = 0; i < 32; i++) hacc[i] = 0ull;

        // stage 1: H = relu(x @ W1_chunk^T + b1)
        for (int k0 = 0; k0 < EE; k0 += 16){
            __syncthreads();
            store_bp16_128(Bp, pf, tid);
            __syncthreads();
            if (k0 + 16 < EE)
                prefetch_bp16_128(pf, w1 + (size_t)jc*256*EE, EE, k0 + 16, tid);
            else
                prefetch_bp16_128(pf, w2 + jc*256, 1024, 0, tid);   // stage2 slab0
            gemm8_tile16<4>(&xs[(8*w)*260 + k0], Bp, l, hacc);
        }
        #pragma unroll
        for (int j = 0; j < 4; j++){
            int c = 2*(l + 32*j);
            float2 bb = *(const float2*)&b1[jc*256 + c];
            #pragma unroll
            for (int rr = 0; rr < 8; rr++){
                float2 f = unpack2(hacc[rr*4 + j]);
                f.x = fmaxf(f.x + bb.x, 0.f);
                f.y = fmaxf(f.y + bb.y, 0.f);
                *(float2*)&Hs[(8*w+rr)*260 + c] = f;   // own-warp rows only
            }
        }
        // stage 2: Y += H @ W2_chunk^T
        for (int k0 = 0; k0 < EE; k0 += 16){
            __syncthreads();
            store_bp16_128(Bp, pf, tid);
            __syncthreads();
            if (k0 + 16 < EE)
                prefetch_bp16_128(pf, w2 + jc*256, 1024, k0 + 16, tid);
            else if (jc < 3)
                prefetch_bp16_128(pf, w1 + (size_t)(jc+1)*256*EE, EE, 0, tid);
            gemm8_tile16<4>(&Hs[(8*w)*260 + k0], Bp, l, yacc);
        }
    }

    float2 b2v[4], g2v[4], bb2v[4];
    #pragma unroll
    for (int j = 0; j < 4; j++){
        int c = 2*(l + 32*j);
        b2v[j]  = *(const float2*)&b2[c];
        g2v[j]  = *(const float2*)&g2[c];
        bb2v[j] = *(const float2*)&bb2[c];
    }
    #pragma unroll
    for (int rr = 0; rr < 8; rr++){
        float vv[8];
        #pragma unroll
        for (int j = 0; j < 4; j++){
            float2 f = unpack2(yacc[rr*4 + j]);
            vv[2*j+0] = f.x + b2v[j].x;
            vv[2*j+1] = f.y + b2v[j].y;
        }
        float s = 0.f;
        #pragma unroll
        for (int q = 0; q < 8; q++) s += vv[q];
        #pragma unroll
        for (int o = 16; o; o >>= 1) s += __shfl_xor_sync(0xffffffffu, s, o);
        float mean = s * (1.f/256.f);
        float vs = 0.f;
        #pragma unroll
        for (int q = 0; q < 8; q++){ float d = vv[q]-mean; vs += d*d; }
        #pragma unroll
        for (int o = 16; o; o >>= 1) vs += __shfl_xor_sync(0xffffffffu, vs, o);
        float inv = rsqrtf(vs*(1.f/256.f) + 1e-5f);
        size_t base = (size_t)(r0 + 8*w + rr)*EE;
        #pragma unroll
        for (int j = 0; j < 4; j++){
            int c = 2*(l + 32*j);
            float2 o2 = make_float2((vv[2*j+0]-mean)*inv*g2v[j].x + bb2v[j].x,
                                    (vv[2*j+1]-mean)*inv*g2v[j].y + bb2v[j].y);
            *(float2*)&g_mm[base + c] = o2;
        }
    }
}

// ---------------- fused heads, f32x2 8-row, pipelined (unchanged) ----------
// grid NN/64. dyn smem: xs[64*260] + Ds[64*260] + Bp f2[128*33] = 166912 B
__global__ void __launch_bounds__(256) heads_kernel(
    const float* __restrict__ dw1, const float* __restrict__ db1,
    const float* __restrict__ dw2, const float* __restrict__ db2,
    const float* __restrict__ sw1, const float* __restrict__ sb1,
    const float* __restrict__ sw2, const float* __restrict__ sb2,
    const float* __restrict__ obs, float* __restrict__ out)
{
    extern __shared__ float sm[];
    float*  xs  = sm;                         // [64][260]
    float*  Ds  = sm + 64*260;                // [64][260]; score aliases stride 132
    float2* Bp  = (float2*)(sm + 2*64*260);   // [128][33]; dec2 aliases W2s [24][260]
    float*  W2s = (float*)Bp;                 // [24][260]
    float*  sw2s = (float*)(Bp + 64*33);      // 128 floats (clear of score-stage Bp)
    int tid = threadIdx.x, l = tid & 31, w = tid >> 5;
    int r0 = blockIdx.x*64;

    load_xs64(xs, g_mm + (size_t)r0*EE, tid);

    int rowD[6], pD[6];
    float dacc[6];
    #pragma unroll
    for (int i = 0; i < 6; i++){
        int idx = tid + 256*i;
        rowD[i] = idx / 24; pD[i] = idx - rowD[i]*24;
        dacc[i] = 0.f;
    }

    float2 pf[16];
    prefetch_bpairs<128>(pf, dw1, EE, 0, tid);
    for (int jc = 0; jc < 2; jc++){
        ull hacc[32];
        #pragma unroll
        for (int i = 0; i < 32; i++) hacc[i] = 0ull;
        for (int k0 = 0; k0 < EE; k0 += 32){
            __syncthreads();
            store_bpairs<128>(Bp, pf, tid);
            __syncthreads();
            if (k0 + 32 < EE)
                prefetch_bpairs<128>(pf, dw1 + (size_t)jc*256*EE, EE, k0 + 32, tid);
            else if (jc == 0)
                prefetch_bpairs<128>(pf, dw1 + (size_t)256*EE, EE, 0, tid);
            else
                prefetch_bpairs<64>(pf, sw1, EE, 0, tid);
            gemm8_tile32<4>(&xs[(8*w)*260 + k0], Bp, l, hacc);
        }
        __syncthreads();
        #pragma unroll
        for (int j = 0; j < 4; j++){
            int c = 2*(l + 32*j);
            float2 bb = *(const float2*)&db1[jc*256 + c];
            #pragma unroll
            for (int rr = 0; rr < 8; rr++){
                float2 f = unpack2(hacc[rr*4 + j]);
                f.x += bb.x; f.y += bb.y;
                f.x = f.x > 0.f ? f.x : expm1f(f.x);
                f.y = f.y > 0.f ? f.y : expm1f(f.y);
                *(float2*)&Ds[(8*w+rr)*260 + c] = f;
            }
        }
        // dec_w2 chunk into W2s as [24][260]
        #pragma unroll
        for (int ii = 0; ii < 24; ii++){
            int li = tid + 256*ii; int p = li >> 8, j2 = li & 255;
            W2s[p*260 + j2] = dw2[(size_t)p*512 + jc*256 + j2];
        }
        __syncthreads();
        #pragma unroll
        for (int i = 0; i < 6; i++){
            float a = 0.f;
            #pragma unroll 8
            for (int j4 = 0; j4 < 256; j4 += 4){
                float4 d  = *(const float4*)&Ds [rowD[i]*260 + j4];
                float4 wv = *(const float4*)&W2s[pD[i]*260  + j4];
                a += d.x*wv.x + d.y*wv.y + d.z*wv.z + d.w*wv.w;
            }
            dacc[i] += a;
        }
        __syncthreads();
    }
    // predictions = deltas + last_pos
    #pragma unroll
    for (int i = 0; i < 6; i++){
        int rg = r0 + rowD[i];
        int b = rg / MM;
        int coord = pD[i] & 1;
        out[(size_t)rg*24 + pD[i]] = dacc[i] + db2[pD[i]] + obs[b*TT*2 + (TT-1)*2 + coord];
    }

    // score head: 256 -> 128 elu -> 1 (W2s dead; sw2s sits past score Bp)
    if (tid < 128) sw2s[tid] = sw2[tid];
    ull sacc[16];
    #pragma unroll
    for (int i = 0; i < 16; i++) sacc[i] = 0ull;
    for (int k0 = 0; k0 < EE; k0 += 32){
        __syncthreads();
        store_bpairs<64>(Bp, pf, tid);
        __syncthreads();
        if (k0 + 32 < EE) prefetch_bpairs<64>(pf, sw1, EE, k0 + 32, tid);
        gemm8_tile32<2>(&xs[(8*w)*260 + k0], Bp, l, sacc);
    }
    __syncthreads();
    float* Ss = Ds;  // alias, stride 132 (16B-aligned rows)
    #pragma unroll
    for (int j = 0; j < 2; j++){
        int c = 2*(l + 32*j);
        float2 bb = *(const float2*)&sb1[c];
        #pragma unroll
        for (int rr = 0; rr < 8; rr++){
            float2 f = unpack2(sacc[rr*2 + j]);
            f.x += bb.x; f.y += bb.y;
            f.x = f.x > 0.f ? f.x : expm1f(f.x);
            f.y = f.y > 0.f ? f.y : expm1f(f.y);
            *(float2*)&Ss[(8*w+rr)*132 + c] = f;
        }
    }
    __syncthreads();
    if (tid < 64){
        float a = 0.f;
        #pragma unroll 8
        for (int j4 = 0; j4 < 128; j4 += 4){
            float4 d  = *(const float4*)&Ss[tid*132 + j4];
            float4 wv = *(const float4*)&sw2s[j4];
            a += d.x*wv.x + d.y*wv.y + d.z*wv.z + d.w*wv.w;
        }
        out[(size_t)NPRED + r0 + tid] = a + sb2[0];
    }
}

// ---------------- host ----------------
extern "C" void kernel_launch(void* const* d_in, const int* in_sizes, int n_in,
                              void* d_out, int out_size)
{
    const float* obs     = (const float*)d_in[0];
    const float* w_ih0   = (const float*)d_in[1];
    const float* w_hh0   = (const float*)d_in[2];
    const float* b_ih0   = (const float*)d_in[3];
    const float* b_hh0   = (const float*)d_in[4];
    const float* w_ih1   = (const float*)d_in[5];
    const float* w_hh1   = (const float*)d_in[6];
    const float* b_ih1   = (const float*)d_in[7];
    const float* b_hh1   = (const float*)d_in[8];
    const float* in_proj_w = (const float*)d_in[9];
    const float* in_proj_b = (const float*)d_in[10];
    const float* out_w   = (const float*)d_in[11];
    const float* out_b   = (const float*)d_in[12];
    const float* ln1_g   = (const float*)d_in[13];
    const float* ln1_b   = (const float*)d_in[14];
    const float* ffn_w1  = (const float*)d_in[15];
    const float* ffn_b1  = (const float*)d_in[16];
    const float* ffn_w2  = (const float*)d_in[17];
    const float* ffn_b2  = (const float*)d_in[18];
    const float* ln2_g   = (const float*)d_in[19];
    const float* ln2_b   = (const float*)d_in[20];
    const float* dec_w1  = (const float*)d_in[21];
    const float* dec_b1  = (const float*)d_in[22];
    const float* dec_w2  = (const float*)d_in[23];
    const float* dec_b2  = (const float*)d_in[24];
    const float* sc_w1   = (const float*)d_in[25];
    const float* sc_b1   = (const float*)d_in[26];
    const float* sc_w2   = (const float*)d_in[27];
    const float* sc_b2   = (const float*)d_in[28];
    float* out = (float*)d_out;

    const int SMEM_MED = (64*260)*4 + 128*33*8;            // 100352
    const int SMEM_FFN = (2*32*260)*4 + 128*17*8;          // 83968
    const int SMEM_BIG = (2*64*260)*4 + 128*33*8;          // 166912
    cudaFuncSetAttribute(lstm_step<0>, cudaFuncAttributeMaxDynamicSharedMemorySize, SMEM_MED);
    cudaFuncSetAttribute(lstm_step<1>, cudaFuncAttributeMaxDynamicSharedMemorySize, SMEM_MED);
    cudaFuncSetAttribute(attn_ln1,     cudaFuncAttributeMaxDynamicSharedMemorySize, SMEM_MED);
    cudaFuncSetAttribute(ffn_ln2,      cudaFuncAttributeMaxDynamicSharedMemorySize, SMEM_FFN);
    cudaFuncSetAttribute(heads_kernel, cudaFuncAttributeMaxDynamicSharedMemorySize, SMEM_BIG);

    // fold v-proj + out-proj (cheap, per-launch)
    fold_cw<<<dim3(8, 8, MM), 256>>>(in_proj_w, out_w);
    fold_cb<<<MM, 256>>>(in_proj_b, out_w, out_b);

    // LSTM layer 0 (t=0 uses c_prev=0 internally; no zeroing pass needed)
    for (int t = 0; t < TT; t++)
        lstm_step<0><<<dim3(BB/64, EE/64), 256, SMEM_MED>>>(obs, w_ih0, w_hh0, b_ih0, b_hh0, t);

    // LSTM layer 1 (final h lands in g_hA after t=7)
    for (int t = 0; t < TT; t++)
        lstm_step<1><<<dim3(BB/64, EE/64), 256, SMEM_MED>>>(obs, w_ih1, w_hh1, b_ih1, b_hh1, t);

    // folded attention + LN1
    attn_ln1<<<dim3(BB/64, MM), 256, SMEM_MED>>>(ln1_g, ln1_b);

    // fused FFN + LN2 (128 threads, 32-row tiles, 2 CTAs/SM)
    ffn_ln2<<<NN/32, 128, SMEM_FFN>>>(ffn_w1, ffn_b1, ffn_w2, ffn_b2, ln2_g, ln2_b);

    // fused heads -> output
    heads_kernel<<<NN/64, 256, SMEM_BIG>>>(dec_w1, dec_b1, dec_w2, dec_b2,
                                           sc_w1, sc_b1, sc_w2, sc_b2, obs, out);
}

// round 11
// speedup vs baseline: 1.0635x; 1.0635x over previous
#include <cuda_runtime.h>
#include <math.h>

#define BB 8192
#define TT 8
#define EE 256
#define MM 20
#define NN (BB*MM)          // 163840 rows after mode expansion
#define NPRED (NN*24)       // predictions element count

typedef unsigned long long ull;

// ---------------- scratch (static device memory; no allocs) ----------------
__device__ float g_hA[BB*EE];
__device__ float g_hB[BB*EE];
__device__ float g_c [BB*EE];
__device__ float g_ys0[(size_t)TT*BB*EE];
__device__ float g_Cw[(size_t)MM*EE*EE];
__device__ float g_Cb[MM*EE];
__device__ float g_x1[(size_t)NN*EE];
__device__ float g_mm[(size_t)NN*EE];

__device__ __forceinline__ float sigf(float x){
    return __fdividef(1.f, 1.f + __expf(-x));
}
__device__ __forceinline__ float tanhfast(float x){
    return __fdividef(2.f, 1.f + __expf(-2.f*x)) - 1.f;
}

// ---------------- packed f32x2 helpers (FFMA2 only reachable via PTX) ------
__device__ __forceinline__ ull pack2(float lo, float hi){
    ull r;
    asm("mov.b64 %0, {%1, %2};" : "=l"(r) : "f"(lo), "f"(hi));
    return r;
}
__device__ __forceinline__ void fma2(ull &d, ull a, ull b){
    asm("fma.rn.f32x2 %0, %1, %2, %0;" : "+l"(d) : "l"(a), "l"(b));
}
__device__ __forceinline__ float2 unpack2(ull v){
    float lo, hi;
    asm("mov.b64 {%0, %1}, %2;" : "=f"(lo), "=f"(hi) : "l"(v));
    return make_float2(lo, hi);
}

// ---------------- B-tile prefetch / store (software pipeline) --------------
// pair p covers source rows (2p, 2p+1); Bp[p*33 + k] = (row2p[k], row2p+1[k])
template<int NP>
__device__ __forceinline__ void prefetch_bpairs(float2* __restrict__ v,
                                                const float* __restrict__ src0,
                                                size_t rowstride, int k0, int tid){
    #pragma unroll
    for (int i = 0; i < NP/8; i++){
        int li = tid + i*256; int p = li >> 5, k = li & 31;
        const float* s = src0 + (size_t)(2*p)*rowstride + k0 + k;
        v[i] = make_float2(s[0], s[rowstride]);
    }
}
template<int NP>
__device__ __forceinline__ void store_bpairs(float2* __restrict__ Bp,
                                             const float2* __restrict__ v, int tid){
    #pragma unroll
    for (int i = 0; i < NP/8; i++){
        int li = tid + i*256; int p = li >> 5, k = li & 31;
        Bp[p*33 + k] = v[i];
    }
}

// Load 64 rows x 256 cols of activations into xs (stride 260), 256 threads.
__device__ __forceinline__ void load_xs64(float* __restrict__ xs,
                                          const float* __restrict__ src,
                                          int tid){
    #pragma unroll
    for (int i = 0; i < 16; i++){
        int li = tid + i*256; int r = li >> 6, c = (li & 63)*4;
        *(float4*)&xs[r*260 + c] = *(const float4*)&src[(size_t)r*EE + c];
    }
}

// 32-deep k-slab of an 8-row x NPAIR-colpair f32x2 GEMM tile.
template<int NPAIR>
__device__ __forceinline__ void gemm8_tile32(
    const float* __restrict__ xr, const float2* __restrict__ Bp,
    int l, ull* acc)
{
    #pragma unroll
    for (int k4 = 0; k4 < 32; k4 += 4){
        float Ar[8][4];
        #pragma unroll
        for (int r = 0; r < 8; r++){
            float4 t = *(const float4*)(xr + r*260 + k4);
            Ar[r][0]=t.x; Ar[r][1]=t.y; Ar[r][2]=t.z; Ar[r][3]=t.w;
        }
        #pragma unroll
        for (int kk = 0; kk < 4; kk++){
            ull bb[NPAIR];
            #pragma unroll
            for (int j = 0; j < NPAIR; j++)
                bb[j] = *(const ull*)&Bp[(l + 32*j)*33 + k4 + kk];
            #pragma unroll
            for (int r = 0; r < 8; r++){
                ull pr = pack2(Ar[r][kk], Ar[r][kk]);
                #pragma unroll
                for (int j = 0; j < NPAIR; j++)
                    fma2(acc[r*NPAIR + j], pr, bb[j]);
            }
        }
    }
}

// ---------------- fold: Cw[m,o,e] = sum_f out_w[m,o,f] * Wv[m,f,e] ----------------
__global__ void fold_cw(const float* __restrict__ inW, const float* __restrict__ outW){
    __shared__ float As[32][33];
    __shared__ float Bs[32][33];
    int m  = blockIdx.z;
    int o0 = blockIdx.y*32;
    int e0 = blockIdx.x*32;
    int tid = threadIdx.x; int tx = tid & 15, ty = tid >> 4;
    float acc00=0.f, acc01=0.f, acc10=0.f, acc11=0.f;
    for (int f0 = 0; f0 < EE; f0 += 32){
        __syncthreads();
        #pragma unroll
        for (int i = 0; i < 4; i++){
            int li = tid + i*256; int r = li >> 5, c = li & 31;
            As[r][c] = outW[((size_t)(m*EE + o0 + r))*EE + f0 + c];
            Bs[r][c] = inW [((size_t)(m*768 + 512 + f0 + r))*EE + e0 + c];
        }
        __syncthreads();
        #pragma unroll
        for (int f = 0; f < 32; f++){
            float a0 = As[ty*2+0][f], a1 = As[ty*2+1][f];
            float b0 = Bs[f][tx*2+0], b1 = Bs[f][tx*2+1];
            acc00 += a0*b0; acc01 += a0*b1; acc10 += a1*b0; acc11 += a1*b1;
        }
    }
    size_t base = ((size_t)(m*EE + o0 + ty*2))*EE + e0 + tx*2;
    g_Cw[base]      = acc00;
    g_Cw[base+1]    = acc01;
    g_Cw[base+EE]   = acc10;
    g_Cw[base+EE+1] = acc11;
}

// Cb[m,o] = sum_f b_v[m,f]*out_w[m,o,f] + out_b[m,o]
__global__ void fold_cb(const float* __restrict__ inB, const float* __restrict__ outW,
                        const float* __restrict__ outB){
    int m = blockIdx.x, o = threadIdx.x;
    const float* wrow = outW + ((size_t)(m*EE + o))*EE;
    const float* bv   = inB + m*768 + 512;
    float acc = 0.f;
    for (int f = 0; f < EE; f++) acc += bv[f]*wrow[f];
    g_Cb[m*EE + o] = acc + outB[m*EE + o];
}

// ---------------- LSTM step, f32x2 8-row tiles (inline B fill, 128 regs) ---
// Block: 64 batch rows x 64 units. grid (BB/64, EE/64), 256 thr, 2 CTAs/SM.
// dyn smem: xs[64*260] + Bp f2[128*33] = 100352 B
template<int LAYER>
__global__ void __launch_bounds__(256) lstm_step(
    const float* __restrict__ xin,
    const float* __restrict__ wih, const float* __restrict__ whh,
    const float* __restrict__ bih, const float* __restrict__ bhh,
    int t)
{
    extern __shared__ float sm[];
    float*  xs = sm;                       // [64][260]
    float2* Bp = (float2*)(sm + 64*260);   // [128][33]
    const float* hin  = (t & 1) ? g_hB : g_hA;
    float*       hout = (t & 1) ? g_hA : g_hB;
    int tid = threadIdx.x, l = tid & 31, w = tid >> 5;
    int br = blockIdx.x*64, u0 = blockIdx.y*64;

    ull acc[32];
    #pragma unroll
    for (int i = 0; i < 32; i++) acc[i] = 0ull;

    const int npass = (LAYER == 1) ? 2 : 1;
    for (int pass = 0; pass < npass; pass++){
        const float* Am; const float* Bm;
        if (LAYER == 1 && pass == 0){ Am = g_ys0 + (size_t)t*BB*EE; Bm = wih; }
        else {
            if (t == 0) continue;          // h == 0, skip recurrent GEMM
            Am = hin; Bm = whh;
        }
        __syncthreads();                   // protect xs from prior-pass readers
        load_xs64(xs, Am + (size_t)br*EE, tid);
        for (int k0 = 0; k0 < EE; k0 += 32){
            __syncthreads();
            #pragma unroll
            for (int i = 0; i < 16; i++){
                int li = tid + i*256; int p = li >> 5, k = li & 31;
                int gate = p >> 5, up = p & 31;
                size_t j0 = (size_t)(gate*256 + u0 + 2*up);
                Bp[p*33 + k] = make_float2(Bm[j0*EE + k0 + k],
                                           Bm[(j0+1)*EE + k0 + k]);
            }
            __syncthreads();
            gemm8_tile32<4>(&xs[(8*w)*260 + k0], Bp, l, acc);
        }
    }

    // epilogue: thread owns rows br+8w+rr (rr<8), units u0+2l, u0+2l+1.
    int ubase = u0 + 2*l;
    float2 bs[4]; float4 w4[4];
    #pragma unroll
    for (int g = 0; g < 4; g++){
        int j = g*256 + ubase;
        bs[g] = make_float2(bih[j] + bhh[j], bih[j+1] + bhh[j+1]);
        if (LAYER == 0) w4[g] = *(const float4*)&wih[2*j];
    }
    #pragma unroll
    for (int rr = 0; rr < 8; rr++){
        int row = br + 8*w + rr;
        float2 pre[4];
        #pragma unroll
        for (int g = 0; g < 4; g++){
            pre[g] = unpack2(acc[rr*4 + g]);
            pre[g].x += bs[g].x; pre[g].y += bs[g].y;
        }
        if (LAYER == 0){
            float2 xv = *(const float2*)&xin[row*TT*2 + t*2];
            #pragma unroll
            for (int g = 0; g < 4; g++){
                pre[g].x += xv.x*w4[g].x + xv.y*w4[g].y;
                pre[g].y += xv.x*w4[g].z + xv.y*w4[g].w;
            }
        }
        int idx = row*EE + ubase;
        float2 cold = make_float2(0.f, 0.f);
        if (t != 0) cold = *(const float2*)&g_c[idx];
        float igx = sigf(pre[0].x), fgx = sigf(pre[1].x);
        float ggx = tanhfast(pre[2].x), ogx = sigf(pre[3].x);
        float igy = sigf(pre[0].y), fgy = sigf(pre[1].y);
        float ggy = tanhfast(pre[2].y), ogy = sigf(pre[3].y);
        float cnx = fgx*cold.x + igx*ggx;
        float cny = fgy*cold.y + igy*ggy;
        float2 hn = make_float2(ogx*tanhfast(cnx), ogy*tanhfast(cny));
        *(float2*)&g_c[idx] = make_float2(cnx, cny);
        *(float2*)&hout[idx] = hn;
        if (LAYER == 0) *(float2*)&g_ys0[(size_t)t*BB*EE + idx] = hn;
    }
}

// ---------------- attn (folded) + LN1, f32x2 8-row, pipelined --------------
// grid (BB/64, MM), 256 threads. dyn smem: xs[64*260] + Bp f2[128*33] = 100352 B
__global__ void __launch_bounds__(256) attn_ln1(const float* __restrict__ g1,
                                                const float* __restrict__ b1){
    extern __shared__ float sm[];
    float*  xs = sm;                       // [64][260]
    float2* Bp = (float2*)(sm + 64*260);   // [128][33]
    int tid = threadIdx.x, l = tid & 31, w = tid >> 5;
    int b0 = blockIdx.x*64, m = blockIdx.y;

    load_xs64(xs, g_hA + (size_t)b0*EE, tid);

    ull acc[32];
    #pragma unroll
    for (int i = 0; i < 32; i++) acc[i] = 0ull;

    const float* cwm = g_Cw + (size_t)m*EE*EE;
    float2 pf[16];
    prefetch_bpairs<128>(pf, cwm, EE, 0, tid);
    for (int k0 = 0; k0 < EE; k0 += 32){
        __syncthreads();
        store_bpairs<128>(Bp, pf, tid);
        __syncthreads();
        if (k0 + 32 < EE) prefetch_bpairs<128>(pf, cwm, EE, k0 + 32, tid);
        gemm8_tile32<4>(&xs[(8*w)*260 + k0], Bp, l, acc);
    }

    float2 cb[4], g1v[4], b1v[4];
    #pragma unroll
    for (int j = 0; j < 4; j++){
        int c = 2*(l + 32*j);
        cb[j]  = *(const float2*)&g_Cb[m*EE + c];
        g1v[j] = *(const float2*)&g1[c];
        b1v[j] = *(const float2*)&b1[c];
    }
    #pragma unroll
    for (int rr = 0; rr < 8; rr++){
        float vv[8];
        #pragma unroll
        for (int j = 0; j < 4; j++){
            float2 f = unpack2(acc[rr*4 + j]);
            vv[2*j+0] = f.x + cb[j].x;
            vv[2*j+1] = f.y + cb[j].y;
        }
        float s = 0.f;
        #pragma unroll
        for (int q = 0; q < 8; q++) s += vv[q];
        #pragma unroll
        for (int o = 16; o; o >>= 1) s += __shfl_xor_sync(0xffffffffu, s, o);
        float mean = s * (1.f/256.f);
        float vs = 0.f;
        #pragma unroll
        for (int q = 0; q < 8; q++){ float d = vv[q]-mean; vs += d*d; }
        #pragma unroll
        for (int o = 16; o; o >>= 1) vs += __shfl_xor_sync(0xffffffffu, vs, o);
        float inv = rsqrtf(vs*(1.f/256.f) + 1e-5f);
        size_t base = ((size_t)(b0 + 8*w + rr)*MM + m)*EE;
        #pragma unroll
        for (int j = 0; j < 4; j++){
            int c = 2*(l + 32*j);
            float2 o2 = make_float2((vv[2*j+0]-mean)*inv*g1v[j].x + b1v[j].x,
                                    (vv[2*j+1]-mean)*inv*g1v[j].y + b1v[j].y);
            *(float2*)&g_x1[base + c] = o2;
        }
    }
}

// ---------------- fused FFN (256->1024 relu ->256) + LN2, pipelined --------
// grid NN/64, 256 threads. dyn smem: xs[64*260]+Hs[64*260]+Bp f2[128*33]=166912 B
__global__ void __launch_bounds__(256) ffn_ln2(
    const float* __restrict__ w1, const float* __restrict__ b1,
    const float* __restrict__ w2, const float* __restrict__ b2,
    const float* __restrict__ g2, const float* __restrict__ bb2)
{
    extern __shared__ float sm[];
    float*  xs = sm;                         // [64][260]
    float*  Hs = sm + 64*260;                // [64][260]
    float2* Bp = (float2*)(sm + 2*64*260);   // [128][33]
    int tid = threadIdx.x, l = tid & 31, w = tid >> 5;
    int r0 = blockIdx.x*64;

    load_xs64(xs, g_x1 + (size_t)r0*EE, tid);

    ull yacc[32];
    #pragma unroll
    for (int i = 0; i < 32; i++) yacc[i] = 0ull;

    float2 pf[16];
    prefetch_bpairs<128>(pf, w1, EE, 0, tid);
    for (int jc = 0; jc < 4; jc++){
        ull hacc[32];
        #pragma unroll
        for (int i = 0; i < 32; i++) hacc[i] = 0ull;

        // stage 1: H = relu(x @ W1_chunk^T + b1)
        for (int k0 = 0; k0 < EE; k0 += 32){
            __syncthreads();
            store_bpairs<128>(Bp, pf, tid);
            __syncthreads();
            if (k0 + 32 < EE)
                prefetch_bpairs<128>(pf, w1 + (size_t)jc*256*EE, EE, k0 + 32, tid);
            else
                prefetch_bpairs<128>(pf, w2 + jc*256, 1024, 0, tid);   // stage2 slab0
            gemm8_tile32<4>(&xs[(8*w)*260 + k0], Bp, l, hacc);
        }
        __syncthreads();
        #pragma unroll
        for (int j = 0; j < 4; j++){
            int c = 2*(l + 32*j);
            float2 bb = *(const float2*)&b1[jc*256 + c];
            #pragma unroll
            for (int rr = 0; rr < 8; rr++){
                float2 f = unpack2(hacc[rr*4 + j]);
                f.x = fmaxf(f.x + bb.x, 0.f);
                f.y = fmaxf(f.y + bb.y, 0.f);
                *(float2*)&Hs[(8*w+rr)*260 + c] = f;
            }
        }
        // stage 2: Y += H @ W2_chunk^T
        for (int k0 = 0; k0 < EE; k0 += 32){
            __syncthreads();
            store_bpairs<128>(Bp, pf, tid);
            __syncthreads();
            if (k0 + 32 < EE)
                prefetch_bpairs<128>(pf, w2 + jc*256, 1024, k0 + 32, tid);
            else if (jc < 3)
                prefetch_bpairs<128>(pf, w1 + (size_t)(jc+1)*256*EE, EE, 0, tid);
            gemm8_tile32<4>(&Hs[(8*w)*260 + k0], Bp, l, yacc);
        }
    }

    float2 b2v[4], g2v[4], bb2v[4];
    #pragma unroll
    for (int j = 0; j < 4; j++){
        int c = 2*(l + 32*j);
        b2v[j]  = *(const float2*)&b2[c];
        g2v[j]  = *(const float2*)&g2[c];
        bb2v[j] = *(const float2*)&bb2[c];
    }
    #pragma unroll
    for (int rr = 0; rr < 8; rr++){
        float vv[8];
        #pragma unroll
        for (int j = 0; j < 4; j++){
            float2 f = unpack2(yacc[rr*4 + j]);
            vv[2*j+0] = f.x + b2v[j].x;
            vv[2*j+1] = f.y + b2v[j].y;
        }
        float s = 0.f;
        #pragma unroll
        for (int q = 0; q < 8; q++) s += vv[q];
        #pragma unroll
        for (int o = 16; o; o >>= 1) s += __shfl_xor_sync(0xffffffffu, s, o);
        float mean = s * (1.f/256.f);
        float vs = 0.f;
        #pragma unroll
        for (int q = 0; q < 8; q++){ float d = vv[q]-mean; vs += d*d; }
        #pragma unroll
        for (int o = 16; o; o >>= 1) vs += __shfl_xor_sync(0xffffffffu, vs, o);
        float inv = rsqrtf(vs*(1.f/256.f) + 1e-5f);
        size_t base = (size_t)(r0 + 8*w + rr)*EE;
        #pragma unroll
        for (int j = 0; j < 4; j++){
            int c = 2*(l + 32*j);
            float2 o2 = make_float2((vv[2*j+0]-mean)*inv*g2v[j].x + bb2v[j].x,
                                    (vv[2*j+1]-mean)*inv*g2v[j].y + bb2v[j].y);
            *(float2*)&g_mm[base + c] = o2;
        }
    }
}

// ---------------- fused heads, f32x2 8-row, pipelined ----------------------
// grid NN/64. dyn smem: xs[64*260] + Ds[64*260] + Bp f2[128*33] = 166912 B
__global__ void __launch_bounds__(256) heads_kernel(
    const float* __restrict__ dw1, const float* __restrict__ db1,
    const float* __restrict__ dw2, const float* __restrict__ db2,
    const float* __restrict__ sw1, const float* __restrict__ sb1,
    const float* __restrict__ sw2, const float* __restrict__ sb2,
    const float* __restrict__ obs, float* __restrict__ out)
{
    extern __shared__ float sm[];
    float*  xs  = sm;                         // [64][260]
    float*  Ds  = sm + 64*260;                // [64][260]; score aliases stride 132
    float2* Bp  = (float2*)(sm + 2*64*260);   // [128][33]; dec2 aliases W2s [24][260]
    float*  W2s = (float*)Bp;                 // [24][260]
    float*  sw2s = (float*)(Bp + 64*33);      // 128 floats (clear of score-stage Bp)
    int tid = threadIdx.x, l = tid & 31, w = tid >> 5;
    int r0 = blockIdx.x*64;

    load_xs64(xs, g_mm + (size_t)r0*EE, tid);

    int rowD[6], pD[6];
    float dacc[6];
    #pragma unroll
    for (int i = 0; i < 6; i++){
        int idx = tid + 256*i;
        rowD[i] = idx / 24; pD[i] = idx - rowD[i]*24;
        dacc[i] = 0.f;
    }

    float2 pf[16];
    prefetch_bpairs<128>(pf, dw1, EE, 0, tid);
    for (int jc = 0; jc < 2; jc++){
        ull hacc[32];
        #pragma unroll
        for (int i = 0; i < 32; i++) hacc[i] = 0ull;
        for (int k0 = 0; k0 < EE; k0 += 32){
            __syncthreads();
            store_bpairs<128>(Bp, pf, tid);
            __syncthreads();
            if (k0 + 32 < EE)
                prefetch_bpairs<128>(pf, dw1 + (size_t)jc*256*EE, EE, k0 + 32, tid);
            else if (jc == 0)
                prefetch_bpairs<128>(pf, dw1 + (size_t)256*EE, EE, 0, tid);
            else
                prefetch_bpairs<64>(pf, sw1, EE, 0, tid);
            gemm8_tile32<4>(&xs[(8*w)*260 + k0], Bp, l, hacc);
        }
        __syncthreads();
        #pragma unroll
        for (int j = 0; j < 4; j++){
            int c = 2*(l + 32*j);
            float2 bb = *(const float2*)&db1[jc*256 + c];
            #pragma unroll
            for (int rr = 0; rr < 8; rr++){
                float2 f = unpack2(hacc[rr*4 + j]);
                f.x += bb.x; f.y += bb.y;
                f.x = f.x > 0.f ? f.x : expm1f(f.x);
                f.y = f.y > 0.f ? f.y : expm1f(f.y);
                *(float2*)&Ds[(8*w+rr)*260 + c] = f;
            }
        }
        // dec_w2 chunk into W2s as [24][260]
        #pragma unroll
        for (int ii = 0; ii < 24; ii++){
            int li = tid + 256*ii; int p = li >> 8, j2 = li & 255;
            W2s[p*260 + j2] = dw2[(size_t)p*512 + jc*256 + j2];
        }
        __syncthreads();
        #pragma unroll
        for (int i = 0; i < 6; i++){
            float a = 0.f;
            #pragma unroll 8
            for (int j4 = 0; j4 < 256; j4 += 4){
                float4 d  = *(const float4*)&Ds [rowD[i]*260 + j4];
                float4 wv = *(const float4*)&W2s[pD[i]*260  + j4];
                a += d.x*wv.x + d.y*wv.y + d.z*wv.z + d.w*wv.w;
            }
            dacc[i] += a;
        }
        __syncthreads();
    }
    // predictions = deltas + last_pos
    #pragma unroll
    for (int i = 0; i < 6; i++){
        int rg = r0 + rowD[i];
        int b = rg / MM;
        int coord = pD[i] & 1;
        out[(size_t)rg*24 + pD[i]] = dacc[i] + db2[pD[i]] + obs[b*TT*2 + (TT-1)*2 + coord];
    }

    // score head: 256 -> 128 elu -> 1 (W2s dead; sw2s sits past score Bp)
    if (tid < 128) sw2s[tid] = sw2[tid];
    ull sacc[16];
    #pragma unroll
    for (int i = 0; i < 16; i++) sacc[i] = 0ull;
    for (int k0 = 0; k0 < EE; k0 += 32){
        __syncthreads();
        store_bpairs<64>(Bp, pf, tid);
        __syncthreads();
        if (k0 + 32 < EE) prefetch_bpairs<64>(pf, sw1, EE, k0 + 32, tid);
        gemm8_tile32<2>(&xs[(8*w)*260 + k0], Bp, l, sacc);
    }
    __syncthreads();
    float* Ss = Ds;  // alias, stride 132 (16B-aligned rows)
    #pragma unroll
    for (int j = 0; j < 2; j++){
        int c = 2*(l + 32*j);
        float2 bb = *(const float2*)&sb1[c];
        #pragma unroll
        for (int rr = 0; rr < 8; rr++){
            float2 f = unpack2(sacc[rr*2 + j]);
            f.x += bb.x; f.y += bb.y;
            f.x = f.x > 0.f ? f.x : expm1f(f.x);
            f.y = f.y > 0.f ? f.y : expm1f(f.y);
            *(float2*)&Ss[(8*w+rr)*132 + c] = f;
        }
    }
    __syncthreads();
    if (tid < 64){
        float a = 0.f;
        #pragma unroll 8
        for (int j4 = 0; j4 < 128; j4 += 4){
            float4 d  = *(const float4*)&Ss[tid*132 + j4];
            float4 wv = *(const float4*)&sw2s[j4];
            a += d.x*wv.x + d.y*wv.y + d.z*wv.z + d.w*wv.w;
        }
        out[(size_t)NPRED + r0 + tid] = a + sb2[0];
    }
}

// ---------------- host ----------------
extern "C" void kernel_launch(void* const* d_in, const int* in_sizes, int n_in,
                              void* d_out, int out_size)
{
    const float* obs     = (const float*)d_in[0];
    const float* w_ih0   = (const float*)d_in[1];
    const float* w_hh0   = (const float*)d_in[2];
    const float* b_ih0   = (const float*)d_in[3];
    const float* b_hh0   = (const float*)d_in[4];
    const float* w_ih1   = (const float*)d_in[5];
    const float* w_hh1   = (const float*)d_in[6];
    const float* b_ih1   = (const float*)d_in[7];
    const float* b_hh1   = (const float*)d_in[8];
    const float* in_proj_w = (const float*)d_in[9];
    const float* in_proj_b = (const float*)d_in[10];
    const float* out_w   = (const float*)d_in[11];
    const float* out_b   = (const float*)d_in[12];
    const float* ln1_g   = (const float*)d_in[13];
    const float* ln1_b   = (const float*)d_in[14];
    const float* ffn_w1  = (const float*)d_in[15];
    const float* ffn_b1  = (const float*)d_in[16];
    const float* ffn_w2  = (const float*)d_in[17];
    const float* ffn_b2  = (const float*)d_in[18];
    const float* ln2_g   = (const float*)d_in[19];
    const float* ln2_b   = (const float*)d_in[20];
    const float* dec_w1  = (const float*)d_in[21];
    const float* dec_b1  = (const float*)d_in[22];
    const float* dec_w2  = (const float*)d_in[23];
    const float* dec_b2  = (const float*)d_in[24];
    const float* sc_w1   = (const float*)d_in[25];
    const float* sc_b1   = (const float*)d_in[26];
    const float* sc_w2   = (const float*)d_in[27];
    const float* sc_b2   = (const float*)d_in[28];
    float* out = (float*)d_out;

    const int SMEM_MED = (64*260)*4 + 128*33*8;    // 100352
    const int SMEM_BIG = (2*64*260)*4 + 128*33*8;  // 166912
    cudaFuncSetAttribute(lstm_step<0>, cudaFuncAttributeMaxDynamicSharedMemorySize, SMEM_MED);
    cudaFuncSetAttribute(lstm_step<1>, cudaFuncAttributeMaxDynamicSharedMemorySize, SMEM_MED);
    cudaFuncSetAttribute(attn_ln1,     cudaFuncAttributeMaxDynamicSharedMemorySize, SMEM_MED);
    cudaFuncSetAttribute(ffn_ln2,      cudaFuncAttributeMaxDynamicSharedMemorySize, SMEM_BIG);
    cudaFuncSetAttribute(heads_kernel, cudaFuncAttributeMaxDynamicSharedMemorySize, SMEM_BIG);

    // fold v-proj + out-proj (cheap, per-launch)
    fold_cw<<<dim3(8, 8, MM), 256>>>(in_proj_w, out_w);
    fold_cb<<<MM, 256>>>(in_proj_b, out_w, out_b);

    // LSTM layer 0 (t=0 uses c_prev=0 internally; no zeroing pass needed)
    for (int t = 0; t < TT; t++)
        lstm_step<0><<<dim3(BB/64, EE/64), 256, SMEM_MED>>>(obs, w_ih0, w_hh0, b_ih0, b_hh0, t);

    // LSTM layer 1 (final h lands in g_hA after t=7)
    for (int t = 0; t < TT; t++)
        lstm_step<1><<<dim3(BB/64, EE/64), 256, SMEM_MED>>>(obs, w_ih1, w_hh1, b_ih1, b_hh1, t);

    // folded attention + LN1
    attn_ln1<<<dim3(BB/64, MM), 256, SMEM_MED>>>(ln1_g, ln1_b);

    // fused FFN + LN2
    ffn_ln2<<<NN/64, 256, SMEM_BIG>>>(ffn_w1, ffn_b1, ffn_w2, ffn_b2, ln2_g, ln2_b);

    // fused heads -> output
    heads_kernel<<<NN/64, 256, SMEM_BIG>>>(dec_w1, dec_b1, dec_w2, dec_b2,
                                           sc_w1, sc_b1, sc_w2, sc_b2, obs, out);
}